// round 12
// baseline (speedup 1.0000x reference)
#include <cuda_runtime.h>
#include <math.h>

#define BB 64
#define NN 16800
#define CC 21
#define TPB 256
#define NBLK 66          // ceil(16800/256)
#define FP32_EPS 1.1920928955078125e-07f
#define FBINS 2048       // linear bins, width 1/128 over [0,16)

// ---------------- scratch (device globals; no allocation) ----------------
// All zero-initialized; every consumer resets after reading -> replay-invariant.
__device__ float    d_bsl1[BB];           // per-batch sum sl1 over positives
__device__ float    d_bce [BB];           // per-batch sum ce  over positives
__device__ int      d_bpos[BB];           // per-batch positive count
__device__ unsigned d_gcnt[BB * FBINS];   // per-batch fine histogram: counts
__device__ float    d_gsum[BB * FBINS];   // per-batch fine histogram: value sums
__device__ float    d_res [BB * 3];
__device__ int      d_btick[BB];          // per-batch ticket
__device__ int      d_done;               // cross-batch ticket

__device__ __forceinline__ float smooth_l1(float d) {
    float a = fabsf(d);
    return (a < 1.f) ? (0.5f * a * a) : (a - 0.5f);
}

// linear equal-width bin over [0,16), width 1/128
__device__ __forceinline__ unsigned fbin(float v) {
    return min((unsigned)(FBINS - 1), (unsigned)(v * 128.0f));
}

// ---------------- single fused kernel ----------------
__global__ void __launch_bounds__(TPB, 8)
k_all(const float4* __restrict__ pb,
      const float4* __restrict__ gb,
      const float4* __restrict__ pl4,
      const int*    __restrict__ gl,
      const float4* __restrict__ anc,
      float* __restrict__ out)
{
    // s_mem reuse: (1) p_labels staging 21504 B
    //              (2) block hist cnt[2048] u32 + sum[2048] f32 = 16 KB
    //              (3) tail: batch hist cnt[2048] + sum[2048] = 16 KB
    __shared__ __align__(16) char s_mem[TPB * CC * 4];
    __shared__ float rs[8], rc[8];
    __shared__ int   rp[8];
    __shared__ unsigned s_wc[8];
    __shared__ float    s_wf[8];
    __shared__ float red[8];
    __shared__ float sA, sC, s_negsum;
    __shared__ int   sP, s_last, s_lastg;

    const int b    = blockIdx.y;
    const int base = blockIdx.x * TPB;
    const int tid  = threadIdx.x;
    const int lane = tid & 31;
    const int w    = tid >> 5;
    const int n    = base + tid;
    const int cnt  = min(TPB, NN - base);

    float* s_lab = (float*)s_mem;

    // ======================= MAIN PHASE =======================
    {
        const float4* src = pl4 + ((size_t)b * NN + base) * CC / 4;
        float4* dst = (float4*)s_lab;
        const int tot4 = (cnt * CC) >> 2;
        for (int i = tid; i < tot4; i += TPB) dst[i] = src[i];
    }
    __syncthreads();

    float sl1 = 0.f, ce = 0.f;
    int pos = 0;
    if (tid < cnt) {
        float4 a = anc[n];
        float4 g = gb[b * NN + n];
        float4 p = pb[b * NN + n];
        float t0 = 10.f * (g.x - a.x) / a.z;
        float t1 = 10.f * (g.y - a.y) / a.w;
        float t2 = 5.f * __logf(g.z / a.z);
        float t3 = 5.f * __logf(g.w / a.w);
        sl1 = smooth_l1(p.x - t0) + smooth_l1(p.y - t1)
            + smooth_l1(p.z - t2) + smooth_l1(p.w - t3);

        const float* x = s_lab + tid * CC;   // stride 21, conflict-free
        float s = 0.f;
        #pragma unroll
        for (int j = 0; j < CC; j++) s += __expf(x[j]);
        int lab = gl[b * NN + n];
        ce = __logf(s) - x[lab];
        pos = (lab > 0);
    }
    const float negv = (tid < cnt) ? (pos ? 0.f : fmaxf(ce, 0.f)) : 0.f;

    // per-block partials -> per-batch scalars (REDG)
    {
        float vsl = pos ? sl1 : 0.f;
        float vce = pos ? ce  : 0.f;
        #pragma unroll
        for (int o = 16; o; o >>= 1) {
            vsl += __shfl_down_sync(0xFFFFFFFFu, vsl, o);
            vce += __shfl_down_sync(0xFFFFFFFFu, vce, o);
        }
        int wp = __popc(__ballot_sync(0xFFFFFFFFu, pos));
        if (lane == 0) { rs[w] = vsl; rc[w] = vce; rp[w] = wp; }
    }
    __syncthreads();   // partials in SMEM, s_lab reads done -> s_mem reusable
    if (tid == 0) {
        float A = 0.f, Cc = 0.f; int P = 0;
        #pragma unroll
        for (int i = 0; i < 8; i++) { A += rs[i]; Cc += rc[i]; P += rp[i]; }
        atomicAdd(&d_bsl1[b], A);
        atomicAdd(&d_bce [b], Cc);
        atomicAdd(&d_bpos[b], P);
    }

    // ---- block-local histogram of this block's 256 neg values ----
    unsigned* hc = (unsigned*)s_mem;          // 2048 u32
    float*    hf = (float*)(hc + FBINS);      // 2048 f32
    for (int i = tid; i < FBINS; i += TPB) { hc[i] = 0u; hf[i] = 0.f; }
    __syncthreads();
    if (tid < cnt) {
        unsigned bin = fbin(negv);
        atomicAdd(&hc[bin], 1u);
        atomicAdd(&hf[bin], negv);
    }
    __syncthreads();
    // merge populated bins to per-batch global hist (spread REDG)
    for (int i = tid; i < FBINS; i += TPB) {
        unsigned c = hc[i];
        if (c) {
            atomicAdd(&d_gcnt[b * FBINS + i], c);
            atomicAdd(&d_gsum[b * FBINS + i], hf[i]);
        }
    }

    // ======================= PER-BATCH TICKET =======================
    if (tid == 0) {
        __threadfence();
        s_last = (atomicAdd(&d_btick[b], 1) == NBLK - 1);
    }
    __syncthreads();
    if (!s_last) return;

    // ======================= TAIL: batch b reduction =======================
    __threadfence();   // see all blocks' merged atomics

    unsigned* scnt = (unsigned*)s_mem;        // 2048 u32
    float*    ssum = (float*)(scnt + FBINS);  // 2048 f32

    // coalesced load of batch hist (L2) + zero for next replay
    for (int i = tid; i < FBINS; i += TPB) {
        const int gi = b * FBINS + i;
        scnt[i] = __ldcg(&d_gcnt[gi]); d_gcnt[gi] = 0u;
        ssum[i] = __ldcg(&d_gsum[gi]); d_gsum[gi] = 0.f;
    }
    if (tid == 0) {
        d_btick[b] = 0;
        sA = __ldcg(&d_bsl1[b]); d_bsl1[b] = 0.f;
        sC = __ldcg(&d_bce [b]); d_bce [b] = 0.f;
        sP = __ldcg(&d_bpos[b]); d_bpos[b] = 0;
        s_negsum = 0.f;
    }
    __syncthreads();

    const int posn = sP;
    const int k0   = min(3 * posn, NN);

    // each thread owns 8 consecutive bins (from SMEM)
    unsigned c8[8]; float f8[8];
    unsigned ct = 0; float ft = 0.f;
    #pragma unroll
    for (int j = 0; j < 8; j++) {
        c8[j] = scnt[tid * 8 + j];
        f8[j] = ssum[tid * 8 + j];
        ct += c8[j]; ft += f8[j];
    }
    // per-warp inclusive suffix over lanes (higher lane = higher bins)
    unsigned sc_ = ct; float sf_ = ft;
    #pragma unroll
    for (int o = 1; o < 32; o <<= 1) {
        unsigned vc = __shfl_down_sync(0xFFFFFFFFu, sc_, o);
        float    vf = __shfl_down_sync(0xFFFFFFFFu, sf_, o);
        if (lane + o < 32) { sc_ += vc; sf_ += vf; }
    }
    if (lane == 0) { s_wc[w] = sc_; s_wf[w] = sf_; }
    __syncthreads();

    if (k0 > 0) {
        unsigned awc = 0; float awf = 0.f;
        #pragma unroll
        for (int j = 0; j < 8; j++) if (j > w) { awc += s_wc[j]; awf += s_wf[j]; }
        const unsigned above_c = awc + (sc_ - ct);
        const float    above_f = awf + (sf_ - ft);

        if (above_c < (unsigned)k0 && above_c + ct >= (unsigned)k0) {
            // exactly one thread: walk own 8 bins high->low; mean closure at boundary
            unsigned cum = above_c; float fa = above_f;
            #pragma unroll
            for (int j = 7; j >= 0; j--) {
                unsigned h = c8[j];
                if (cum + h >= (unsigned)k0) {
                    const float mean = f8[j] / (float)h;
                    s_negsum = fa + (float)(k0 - (int)cum) * mean;
                    break;
                }
                cum += h; fa += f8[j];
            }
        }
    }
    __syncthreads();

    if (tid == 0) {
        float lb = sA;
        float ll = sC + s_negsum;
        float nm = (posn > 0) ? 1.f : 0.f;
        float pf = fmaxf((float)posn, FP32_EPS);
        d_res[b * 3 + 0] = (lb + ll) * nm / pf;
        d_res[b * 3 + 1] = lb * nm / pf;
        d_res[b * 3 + 2] = ll * nm / pf;
        __threadfence();
        s_lastg = (atomicAdd(&d_done, 1) == BB - 1);
    }
    __syncthreads();

    // ======================= CROSS-BATCH FINAL (last batch) =======================
    if (s_lastg) {
        __threadfence();
        float lt = 0.f, vb = 0.f, vl = 0.f;
        if (tid < BB) {
            volatile float* r = d_res;
            lt = r[tid * 3 + 0];
            vb = r[tid * 3 + 1];
            vl = r[tid * 3 + 2];
        }
        if (tid < 64) {
            #pragma unroll
            for (int o = 16; o; o >>= 1) {
                lt += __shfl_down_sync(0xFFFFFFFFu, lt, o);
                vb += __shfl_down_sync(0xFFFFFFFFu, vb, o);
                vl += __shfl_down_sync(0xFFFFFFFFu, vl, o);
            }
            if ((tid & 31) == 0) {
                red[tid >> 5]       = lt;
                red[(tid >> 5) + 2] = vb;
                red[(tid >> 5) + 4] = vl;
            }
        }
        __syncthreads();
        if (tid == 0) {
            out[0] = (red[0] + red[1]) * (1.f / 64.f);
            out[1] = (red[2] + red[3]) * (1.f / 64.f);
            out[2] = (red[4] + red[5]) * (1.f / 64.f);
            d_done = 0;   // self-reset for next graph replay
        }
    }
}

// ---------------- launch ----------------
extern "C" void kernel_launch(void* const* d_in, const int* in_sizes, int n_in,
                              void* d_out, int out_size) {
    const float4* pb  = (const float4*)d_in[0];
    const float4* gb  = (const float4*)d_in[1];
    const float4* pl4 = (const float4*)d_in[2];
    const int*    gl  = (const int*)d_in[3];
    const float4* anc = (const float4*)d_in[4];
    float* out = (float*)d_out;

    dim3 gBN(NBLK, BB);
    k_all<<<gBN, TPB>>>(pb, gb, pl4, gl, anc, out);
}

// round 13
// speedup vs baseline: 1.9209x; 1.9209x over previous
#include <cuda_runtime.h>
#include <math.h>

#define BB 64
#define NN 16800
#define CC 21
#define TPB 256
#define NBLK 66          // ceil(16800/256)
#define FP32_EPS 1.1920928955078125e-07f
#define FBINS 512        // linear bins, width 1/32 over [0,16)

// ---------------- scratch (device globals; no allocation) ----------------
__device__ float    d_psl1[BB * NBLK];
__device__ float    d_pce [BB * NBLK];
__device__ int      d_ppos[BB * NBLK];
__device__ unsigned d_gcnt[BB * FBINS];   // zero-init; k_fin re-zeros (replay-invariant)
__device__ float    d_gsum[BB * FBINS];   // zero-init; k_fin re-zeros
__device__ float    d_res [BB * 3];
__device__ int      d_done;               // ticket (self-resetting)

__device__ __forceinline__ float smooth_l1(float d) {
    float a = fabsf(d);
    return (a < 1.f) ? (0.5f * a * a) : (a - 0.5f);
}

// linear equal-width bin over [0,16), width 1/32
__device__ __forceinline__ unsigned fbin(float v) {
    return min((unsigned)(FBINS - 1), (unsigned)(v * 32.0f));
}

// ---------------- main: sl1 + ce + partials + fused 512-bin histogram ----------------
__global__ void __launch_bounds__(TPB, 8)
k_main(const float4* __restrict__ pb,
       const float4* __restrict__ gb,
       const float4* __restrict__ pl4,
       const int*    __restrict__ gl,
       const float4* __restrict__ anc)
{
    // s_mem reuse: (1) p_labels staging 21504 B; (2) hist cnt[512] u32 + sum[512] f32 = 4 KB
    __shared__ __align__(16) char s_mem[TPB * CC * 4];
    __shared__ float rs[8], rc[8];
    __shared__ int   rp[8];

    const int b    = blockIdx.y;
    const int base = blockIdx.x * TPB;
    const int tid  = threadIdx.x;
    const int lane = tid & 31;
    const int w    = tid >> 5;
    const int n    = base + tid;
    const int cnt  = min(TPB, NN - base);

    float* s_lab = (float*)s_mem;

    {
        const float4* src = pl4 + ((size_t)b * NN + base) * CC / 4;
        float4* dst = (float4*)s_lab;
        const int tot4 = (cnt * CC) >> 2;
        for (int i = tid; i < tot4; i += TPB) dst[i] = src[i];
    }
    __syncthreads();

    float sl1 = 0.f, ce = 0.f;
    int pos = 0;
    if (tid < cnt) {
        float4 a = anc[n];
        float4 g = gb[b * NN + n];
        float4 p = pb[b * NN + n];
        float t0 = 10.f * (g.x - a.x) / a.z;
        float t1 = 10.f * (g.y - a.y) / a.w;
        float t2 = 5.f * __logf(g.z / a.z);
        float t3 = 5.f * __logf(g.w / a.w);
        sl1 = smooth_l1(p.x - t0) + smooth_l1(p.y - t1)
            + smooth_l1(p.z - t2) + smooth_l1(p.w - t3);

        const float* x = s_lab + tid * CC;   // stride 21, conflict-free
        float s = 0.f;
        #pragma unroll
        for (int j = 0; j < CC; j++) s += __expf(x[j]);
        int lab = gl[b * NN + n];
        ce = __logf(s) - x[lab];
        pos = (lab > 0);
    }
    const float negv = pos ? 0.f : fmaxf(ce, 0.f);

    // per-block partials (positives)
    {
        float vsl = pos ? sl1 : 0.f;
        float vce = pos ? ce  : 0.f;
        #pragma unroll
        for (int o = 16; o; o >>= 1) {
            vsl += __shfl_down_sync(0xFFFFFFFFu, vsl, o);
            vce += __shfl_down_sync(0xFFFFFFFFu, vce, o);
        }
        int wp = __popc(__ballot_sync(0xFFFFFFFFu, pos));
        if (lane == 0) { rs[w] = vsl; rc[w] = vce; rp[w] = wp; }
    }
    __syncthreads();   // partials visible; s_lab reads done -> s_mem reusable
    if (tid == 0) {
        float A = 0.f, Cc = 0.f; int P = 0;
        #pragma unroll
        for (int i = 0; i < 8; i++) { A += rs[i]; Cc += rc[i]; P += rp[i]; }
        const int idx = b * NBLK + blockIdx.x;
        d_psl1[idx] = A;
        d_pce [idx] = Cc;
        d_ppos[idx] = P;
    }

    // ---- block-local 512-bin histogram of this block's neg values ----
    unsigned* hc = (unsigned*)s_mem;          // 512 u32
    float*    hf = (float*)(hc + FBINS);      // 512 f32
    for (int i = tid; i < FBINS; i += TPB) { hc[i] = 0u; hf[i] = 0.f; }
    __syncthreads();
    if (tid < cnt) {
        unsigned bin = fbin(negv);
        atomicAdd(&hc[bin], 1u);
        atomicAdd(&hf[bin], negv);
    }
    __syncthreads();
    // merge populated bins to per-batch global hist (spread REDG)
    for (int i = tid; i < FBINS; i += TPB) {
        unsigned c = hc[i];
        if (c) {
            atomicAdd(&d_gcnt[b * FBINS + i], c);
            atomicAdd(&d_gsum[b * FBINS + i], hf[i]);
        }
    }
}

// ---------------- fin: one block per batch; ~0.6 MB total traffic ----------------
__global__ void __launch_bounds__(TPB)
k_fin(float* __restrict__ out)
{
    __shared__ float a66[NBLK], c66[NBLK];
    __shared__ int   p66[NBLK];
    __shared__ unsigned s_wc[8];
    __shared__ float    s_wf[8];
    __shared__ float red[8];
    __shared__ float sA, sC, s_negsum;
    __shared__ int   sP, s_lastg;

    const int b    = blockIdx.x;
    const int tid  = threadIdx.x;
    const int lane = tid & 31;
    const int w    = tid >> 5;

    // thread owns 2 consecutive bins; load (L2) + zero for replay
    unsigned c2[2]; float f2[2];
    {
        const int gbase = b * FBINS + tid * 2;
        #pragma unroll
        for (int j = 0; j < 2; j++) {
            c2[j] = d_gcnt[gbase + j];
            f2[j] = d_gsum[gbase + j];
            d_gcnt[gbase + j] = 0u;
            d_gsum[gbase + j] = 0.f;
        }
    }
    if (tid < NBLK) {
        const int idx = b * NBLK + tid;
        a66[tid] = d_psl1[idx];
        c66[tid] = d_pce [idx];
        p66[tid] = d_ppos[idx];
    }
    if (tid == 0) s_negsum = 0.f;
    __syncthreads();

    // reduce partials (warp 0)
    if (tid < 32) {
        float A  = a66[tid] + a66[tid + 32] + ((tid < 2) ? a66[tid + 64] : 0.f);
        float Cc = c66[tid] + c66[tid + 32] + ((tid < 2) ? c66[tid + 64] : 0.f);
        int   P  = p66[tid] + p66[tid + 32] + ((tid < 2) ? p66[tid + 64] : 0);
        #pragma unroll
        for (int o = 16; o; o >>= 1) {
            A  += __shfl_down_sync(0xFFFFFFFFu, A, o);
            Cc += __shfl_down_sync(0xFFFFFFFFu, Cc, o);
            P  += __shfl_down_sync(0xFFFFFFFFu, P, o);
        }
        if (tid == 0) { sA = A; sC = Cc; sP = P; }
    }

    // per-warp inclusive suffix over lanes (higher lane = higher bins)
    const unsigned ct = c2[0] + c2[1];
    const float    ft = f2[0] + f2[1];
    unsigned sc_ = ct; float sf_ = ft;
    #pragma unroll
    for (int o = 1; o < 32; o <<= 1) {
        unsigned vc = __shfl_down_sync(0xFFFFFFFFu, sc_, o);
        float    vf = __shfl_down_sync(0xFFFFFFFFu, sf_, o);
        if (lane + o < 32) { sc_ += vc; sf_ += vf; }
    }
    if (lane == 0) { s_wc[w] = sc_; s_wf[w] = sf_; }
    __syncthreads();

    const int posn = sP;
    const int k0   = min(3 * posn, NN);

    if (k0 > 0) {
        unsigned awc = 0; float awf = 0.f;
        #pragma unroll
        for (int j = 0; j < 8; j++) if (j > w) { awc += s_wc[j]; awf += s_wf[j]; }
        const unsigned above_c = awc + (sc_ - ct);
        const float    above_f = awf + (sf_ - ft);

        if (above_c < (unsigned)k0 && above_c + ct >= (unsigned)k0) {
            // exactly one thread: walk own 2 bins high->low; mean closure at boundary
            unsigned cum = above_c; float fa = above_f;
            #pragma unroll
            for (int j = 1; j >= 0; j--) {
                unsigned h = c2[j];
                if (cum + h >= (unsigned)k0) {
                    const float mean = f2[j] / (float)h;
                    s_negsum = fa + (float)(k0 - (int)cum) * mean;
                    break;
                }
                cum += h; fa += f2[j];
            }
        }
    }
    __syncthreads();

    if (tid == 0) {
        float lb = sA;
        float ll = sC + s_negsum;
        float nm = (posn > 0) ? 1.f : 0.f;
        float pf = fmaxf((float)posn, FP32_EPS);
        d_res[b * 3 + 0] = (lb + ll) * nm / pf;
        d_res[b * 3 + 1] = lb * nm / pf;
        d_res[b * 3 + 2] = ll * nm / pf;
        __threadfence();
        s_lastg = (atomicAdd(&d_done, 1) == BB - 1);
    }
    __syncthreads();

    // fused cross-batch final reduction (last block to finish)
    if (s_lastg) {
        __threadfence();
        float lt = 0.f, vb = 0.f, vl = 0.f;
        if (tid < BB) {
            volatile float* r = d_res;
            lt = r[tid * 3 + 0];
            vb = r[tid * 3 + 1];
            vl = r[tid * 3 + 2];
        }
        if (tid < 64) {
            #pragma unroll
            for (int o = 16; o; o >>= 1) {
                lt += __shfl_down_sync(0xFFFFFFFFu, lt, o);
                vb += __shfl_down_sync(0xFFFFFFFFu, vb, o);
                vl += __shfl_down_sync(0xFFFFFFFFu, vl, o);
            }
            if ((tid & 31) == 0) {
                red[tid >> 5]       = lt;
                red[(tid >> 5) + 2] = vb;
                red[(tid >> 5) + 4] = vl;
            }
        }
        __syncthreads();
        if (tid == 0) {
            out[0] = (red[0] + red[1]) * (1.f / 64.f);
            out[1] = (red[2] + red[3]) * (1.f / 64.f);
            out[2] = (red[4] + red[5]) * (1.f / 64.f);
            d_done = 0;   // self-reset for next graph replay
        }
    }
}

// ---------------- launch ----------------
extern "C" void kernel_launch(void* const* d_in, const int* in_sizes, int n_in,
                              void* d_out, int out_size) {
    const float4* pb  = (const float4*)d_in[0];
    const float4* gb  = (const float4*)d_in[1];
    const float4* pl4 = (const float4*)d_in[2];
    const int*    gl  = (const int*)d_in[3];
    const float4* anc = (const float4*)d_in[4];
    float* out = (float*)d_out;

    dim3 gBN(NBLK, BB);
    k_main<<<gBN, TPB>>>(pb, gb, pl4, gl, anc);
    k_fin<<<BB, TPB>>>(out);
}